// round 3
// baseline (speedup 1.0000x reference)
#include <cuda_runtime.h>
#include <math.h>

#define NUM_B 2
#define NUM_C 256
#define NUM_H 256
#define NUM_W 256
#define NUM_N 512
#define OUT_H 7
#define OUT_W 7
#define NBIN 49
#define HW (NUM_H * NUM_W)
#define CHW (NUM_C * HW)
#define C_HALF 128

// per-bin metadata bits
#define MB_TOPN    4
#define MB_BOTN    8
#define MB_SAMECOL 16

__global__ __launch_bounds__(256) void rroi_pool_kernel(
    const float* __restrict__ x,
    const float* __restrict__ boxes,
    float* __restrict__ out)
{
    __shared__ int4   s_off[NBIN];   // x: top float4 off, y: bottom float4 off,
                                     // z: top extra (ot+cr), w: bottom extra (ob+cr)
    __shared__ float4 s_w[NBIN];     // weights lt, rt, rb, lb (validity folded)
    __shared__ int    s_meta[NBIN];  // j | topn<<2 | botn<<3 | samecol<<4

    const int roi  = blockIdx.x >> 1;
    const int half = blockIdx.x & 1;
    const int tid  = threadIdx.x;

    if (tid < NBIN) {
        const float* bx = boxes + roi * 5;
        float cx  = __fmul_rn(bx[0], 0.25f);
        float cy  = __fmul_rn(bx[1], 0.25f);
        float w   = __fmul_rn(bx[2], 0.25f);
        float h   = __fmul_rn(bx[3], 0.25f);
        float ang = __fmul_rn(bx[4], 0.017453292519943295f);

        float Sx = __fdiv_rn(w, 7.0f);
        float Sy = __fdiv_rn(h, 7.0f);
        float ca = cosf(ang);
        float sa = sinf(ang);

        const float dxc = -3.5f;
        const float dyc = -3.5f;

        float M00 = __fmul_rn(ca, Sx);
        float M01 = __fmul_rn(sa, Sy);
        float M02 = __fadd_rn(__fadd_rn(__fmul_rn(__fmul_rn(ca, Sx), dxc),
                                        __fmul_rn(__fmul_rn(sa, Sy), dyc)), cx);
        float M10 = __fmul_rn(-sa, Sx);
        float M11 = __fmul_rn(ca, Sy);
        float M12 = __fadd_rn(__fadd_rn(__fmul_rn(__fmul_rn(-sa, Sx), dxc),
                                        __fmul_rn(__fmul_rn(ca, Sy), dyc)), cy);

        int ph = tid / OUT_W;
        int pw = tid - ph * OUT_W;

        const float offx[4] = {0.f, 0.f, 1.f, 1.f};
        const float offy[4] = {0.f, 1.f, 0.f, 1.f};

        float minX =  3.0e38f, maxX = -3.0e38f;
        float minY =  3.0e38f, maxY = -3.0e38f;
        #pragma unroll
        for (int k = 0; k < 4; ++k) {
            float pwc = (float)pw + offx[k];
            float phc = (float)ph + offy[k];
            float X = __fadd_rn(__fadd_rn(__fmul_rn(M00, pwc), __fmul_rn(M01, phc)), M02);
            float Y = __fadd_rn(__fadd_rn(__fmul_rn(M10, pwc), __fmul_rn(M11, phc)), M12);
            minX = fminf(minX, X); maxX = fmaxf(maxX, X);
            minY = fminf(minY, Y); maxY = fmaxf(maxY, Y);
        }

        float lM = fmaxf(rintf(minX), 0.0f);
        float rM = fminf(rintf(maxX), (float)(NUM_W - 1));
        float tM = fmaxf(rintf(minY), 0.0f);
        float bM = fminf(rintf(maxY), (float)(NUM_H - 1));

        float bcx = __fmul_rn(__fadd_rn(lM, rM), 0.5f);
        float bcy = __fmul_rn(__fadd_rn(tM, bM), 0.5f);

        float flx = floorf(bcx);
        float fly = floorf(bcy);
        int il = (int)flx;
        int it = (int)fly;
        int ir = (int)ceilf(bcx);
        int ib = (int)ceilf(bcy);
        float rx = __fsub_rn(bcx, flx);
        float ry = __fsub_rn(bcy, fly);

        float omrx = __fsub_rn(1.0f, rx);
        float omry = __fsub_rn(1.0f, ry);
        float wlt = __fmul_rn(omrx, omry);
        float wrt = __fmul_rn(rx,   omry);
        float wrb = __fmul_rn(rx,   ry);
        float wlb = __fmul_rn(omrx, ry);

        bool vl = (il >= 0) && (il < NUM_W);
        bool vr = (ir >= 0) && (ir < NUM_W);
        bool vt = (it >= 0) && (it < NUM_H);
        bool vb = (ib >= 0) && (ib < NUM_H);

        int cl = min(max(il, 0), NUM_W - 1);
        int cr = min(max(ir, 0), NUM_W - 1);
        int ct = min(max(it, 0), NUM_H - 1);
        int cb = min(max(ib, 0), NUM_H - 1);

        float4 wv;
        wv.x = (vt && vl) ? wlt : 0.0f;
        wv.y = (vt && vr) ? wrt : 0.0f;
        wv.z = (vb && vr) ? wrb : 0.0f;
        wv.w = (vb && vl) ? wlb : 0.0f;
        s_w[tid] = wv;

        int ot  = ct * NUM_W;
        int ob2 = cb * NUM_W;
        int cl4 = cl & ~3;
        int j   = cl & 3;

        int4 o;
        o.x = ot  + cl4;   // top aligned float4 (float index)
        o.y = ob2 + cl4;   // bottom aligned float4
        o.z = ot  + cr;    // top extra scalar (j==3 fallback)
        o.w = ob2 + cr;    // bottom extra scalar
        s_off[tid] = o;

        bool topn    = (wv.x != 0.0f) || (wv.y != 0.0f);
        bool botn    = (wv.z != 0.0f) || (wv.w != 0.0f);
        bool samecol = (cr == cl);
        s_meta[tid] = j | (topn ? MB_TOPN : 0) | (botn ? MB_BOTN : 0)
                        | (samecol ? MB_SAMECOL : 0);
    }
    __syncthreads();

    if (tid >= 5 * NBIN) return;   // 245 active threads

    const int bin = tid % NBIN;
    const int c0  = tid / NBIN;    // 0..4

    const int4   o    = s_off[bin];
    const float4 wv   = s_w[bin];
    const int    meta = s_meta[bin];
    const int  j       = meta & 3;
    const bool topn    = (meta & MB_TOPN)    != 0;
    const bool botn    = (meta & MB_BOTN)    != 0;
    const bool samecol = (meta & MB_SAMECOL) != 0;
    const bool xt = topn && !samecol && (j == 3);  // need top scalar fallback
    const bool xb = botn && !samecol && (j == 3);  // need bottom scalar fallback

    const float* fb = x + (size_t)(roi >> 9) * CHW;
    float* ob = out + (size_t)roi * (NUM_C * NBIN) + bin;

    const int cbeg = half * C_HALF + c0;
    const int cend = half * C_HALF + C_HALF;

    #pragma unroll 4
    for (int c = cbeg; c < cend; c += 5) {
        const float* pc = fb + (size_t)c * HW;

        float4 t4 = make_float4(0.f, 0.f, 0.f, 0.f);
        float4 b4 = make_float4(0.f, 0.f, 0.f, 0.f);
        if (topn) t4 = *reinterpret_cast<const float4*>(pc + o.x);
        if (botn) b4 = *reinterpret_cast<const float4*>(pc + o.y);
        float rtx = 0.f, rbx = 0.f;
        if (xt) rtx = pc[o.z];
        if (xb) rbx = pc[o.w];

        float lt = (j == 0) ? t4.x : (j == 1) ? t4.y : (j == 2) ? t4.z : t4.w;
        float lb = (j == 0) ? b4.x : (j == 1) ? b4.y : (j == 2) ? b4.z : b4.w;
        float rt = samecol ? lt : ((j == 0) ? t4.y : (j == 1) ? t4.z : (j == 2) ? t4.w : rtx);
        float rb = samecol ? lb : ((j == 0) ? b4.y : (j == 1) ? b4.z : (j == 2) ? b4.w : rbx);

        float v = lt * wv.x + rt * wv.y + rb * wv.z + lb * wv.w;
        ob[(size_t)c * NBIN] = fmaxf(v, 0.0f);
    }
}

extern "C" void kernel_launch(void* const* d_in, const int* in_sizes, int n_in,
                              void* d_out, int out_size) {
    const float* x     = (const float*)d_in[0];   // (2,256,256,256) f32
    const float* boxes = (const float*)d_in[1];   // (2,512,5) f32
    float* out = (float*)d_out;                   // (1024,256,7,7) f32
    (void)in_sizes; (void)n_in; (void)out_size;

    rroi_pool_kernel<<<NUM_B * NUM_N * 2, 256>>>(x, boxes, out);
}

// round 4
// speedup vs baseline: 1.1395x; 1.1395x over previous
#include <cuda_runtime.h>
#include <math.h>

#define NUM_B 2
#define NUM_C 256
#define NUM_H 256
#define NUM_W 256
#define NUM_N 512
#define OUT_H 7
#define OUT_W 7
#define NBIN 49
#define HW (NUM_H * NUM_W)
#define CHW (NUM_C * HW)
#define C_HALF 128

#define MB_TOPN 1
#define MB_BOTN 2
#define MB_XT   4
#define MB_XB   8

__global__ __launch_bounds__(256) void rroi_pool_kernel(
    const float* __restrict__ x,
    const float* __restrict__ boxes,
    float* __restrict__ out)
{
    __shared__ int4   s_off[NBIN];  // top f4 off, bottom f4 off, top extra, bottom extra
    __shared__ float4 s_wt[NBIN];   // lane weights for top float4
    __shared__ float4 s_wb[NBIN];   // lane weights for bottom float4
    __shared__ float2 s_wx[NBIN];   // scalar fallback weights (top, bottom)
    __shared__ int    s_meta[NBIN];

    const int roi  = blockIdx.x >> 1;
    const int half = blockIdx.x & 1;
    const int tid  = threadIdx.x;

    if (tid < NBIN) {
        const float* bx = boxes + roi * 5;
        float cx  = __fmul_rn(bx[0], 0.25f);
        float cy  = __fmul_rn(bx[1], 0.25f);
        float w   = __fmul_rn(bx[2], 0.25f);
        float h   = __fmul_rn(bx[3], 0.25f);
        float ang = __fmul_rn(bx[4], 0.017453292519943295f);

        float Sx = __fdiv_rn(w, 7.0f);
        float Sy = __fdiv_rn(h, 7.0f);
        float ca = cosf(ang);
        float sa = sinf(ang);

        const float dxc = -3.5f;
        const float dyc = -3.5f;

        float M00 = __fmul_rn(ca, Sx);
        float M01 = __fmul_rn(sa, Sy);
        float M02 = __fadd_rn(__fadd_rn(__fmul_rn(__fmul_rn(ca, Sx), dxc),
                                        __fmul_rn(__fmul_rn(sa, Sy), dyc)), cx);
        float M10 = __fmul_rn(-sa, Sx);
        float M11 = __fmul_rn(ca, Sy);
        float M12 = __fadd_rn(__fadd_rn(__fmul_rn(__fmul_rn(-sa, Sx), dxc),
                                        __fmul_rn(__fmul_rn(ca, Sy), dyc)), cy);

        int ph = tid / OUT_W;
        int pw = tid - ph * OUT_W;

        const float offx[4] = {0.f, 0.f, 1.f, 1.f};
        const float offy[4] = {0.f, 1.f, 0.f, 1.f};

        float minX =  3.0e38f, maxX = -3.0e38f;
        float minY =  3.0e38f, maxY = -3.0e38f;
        #pragma unroll
        for (int k = 0; k < 4; ++k) {
            float pwc = (float)pw + offx[k];
            float phc = (float)ph + offy[k];
            float X = __fadd_rn(__fadd_rn(__fmul_rn(M00, pwc), __fmul_rn(M01, phc)), M02);
            float Y = __fadd_rn(__fadd_rn(__fmul_rn(M10, pwc), __fmul_rn(M11, phc)), M12);
            minX = fminf(minX, X); maxX = fmaxf(maxX, X);
            minY = fminf(minY, Y); maxY = fmaxf(maxY, Y);
        }

        float lM = fmaxf(rintf(minX), 0.0f);
        float rM = fminf(rintf(maxX), (float)(NUM_W - 1));
        float tM = fmaxf(rintf(minY), 0.0f);
        float bM = fminf(rintf(maxY), (float)(NUM_H - 1));

        float bcx = __fmul_rn(__fadd_rn(lM, rM), 0.5f);
        float bcy = __fmul_rn(__fadd_rn(tM, bM), 0.5f);

        float flx = floorf(bcx);
        float fly = floorf(bcy);
        int il = (int)flx;
        int it = (int)fly;
        int ir = (int)ceilf(bcx);
        int ib = (int)ceilf(bcy);
        float rx = __fsub_rn(bcx, flx);
        float ry = __fsub_rn(bcy, fly);

        float omrx = __fsub_rn(1.0f, rx);
        float omry = __fsub_rn(1.0f, ry);
        float wlt = __fmul_rn(omrx, omry);
        float wrt = __fmul_rn(rx,   omry);
        float wrb = __fmul_rn(rx,   ry);
        float wlb = __fmul_rn(omrx, ry);

        bool vl = (il >= 0) && (il < NUM_W);
        bool vr = (ir >= 0) && (ir < NUM_W);
        bool vt = (it >= 0) && (it < NUM_H);
        bool vb = (ib >= 0) && (ib < NUM_H);

        int cl = min(max(il, 0), NUM_W - 1);
        int cr = min(max(ir, 0), NUM_W - 1);
        int ct = min(max(it, 0), NUM_H - 1);
        int cb = min(max(ib, 0), NUM_H - 1);

        // validity-folded corner weights
        float Wlt = (vt && vl) ? wlt : 0.0f;
        float Wrt = (vt && vr) ? wrt : 0.0f;
        float Wrb = (vb && vr) ? wrb : 0.0f;
        float Wlb = (vb && vl) ? wlb : 0.0f;

        int ot  = ct * NUM_W;
        int ob2 = cb * NUM_W;
        int cl4 = cl & ~3;
        int j   = cl & 3;
        bool samecol = (cr == cl);

        // Build per-lane weight vectors: weight moves to the data's lane.
        float wt[4] = {0.f, 0.f, 0.f, 0.f};
        float wb[4] = {0.f, 0.f, 0.f, 0.f};
        float wxt = 0.f, wxb = 0.f;

        wt[j] = Wlt;
        wb[j] = Wlb;
        if (samecol) {
            wt[j] += Wrt;     // exact: rt == lt value
            wb[j] += Wrb;
        } else if (j < 3) {
            wt[j + 1] = Wrt;
            wb[j + 1] = Wrb;
        } else {
            wxt = Wrt;
            wxb = Wrb;
        }

        bool topn = (Wlt != 0.0f) || (Wrt != 0.0f);
        bool botn = (Wlb != 0.0f) || (Wrb != 0.0f);
        bool xt   = topn && (wxt != 0.0f);
        bool xb   = botn && (wxb != 0.0f);

        s_wt[tid] = make_float4(wt[0], wt[1], wt[2], wt[3]);
        s_wb[tid] = make_float4(wb[0], wb[1], wb[2], wb[3]);
        s_wx[tid] = make_float2(wxt, wxb);

        int4 o;
        o.x = ot  + cl4;
        o.y = ob2 + cl4;
        o.z = ot  + cr;
        o.w = ob2 + cr;
        s_off[tid] = o;

        s_meta[tid] = (topn ? MB_TOPN : 0) | (botn ? MB_BOTN : 0)
                    | (xt ? MB_XT : 0) | (xb ? MB_XB : 0);
    }
    __syncthreads();

    if (tid >= 5 * NBIN) return;   // 245 active threads

    const int bin = tid % NBIN;
    const int c0  = tid / NBIN;    // 0..4

    const int4   o   = s_off[bin];
    const float4 wt4 = s_wt[bin];
    const float4 wb4 = s_wb[bin];
    const float2 wx  = s_wx[bin];
    const int    m   = s_meta[bin];
    const bool topn = (m & MB_TOPN) != 0;
    const bool botn = (m & MB_BOTN) != 0;
    const bool xt   = (m & MB_XT)   != 0;
    const bool xb   = (m & MB_XB)   != 0;

    const float* fb = x + (size_t)(roi >> 9) * CHW;
    float* ob = out + (size_t)roi * (NUM_C * NBIN) + bin;

    const int cbeg = half * C_HALF + c0;
    const int cend = half * C_HALF + C_HALF;

    #pragma unroll 4
    for (int c = cbeg; c < cend; c += 5) {
        const float* pc = fb + (size_t)c * HW;

        float4 t4 = make_float4(0.f, 0.f, 0.f, 0.f);
        float4 b4 = make_float4(0.f, 0.f, 0.f, 0.f);
        float rtx = 0.f, rbx = 0.f;
        if (topn) t4 = *reinterpret_cast<const float4*>(pc + o.x);
        if (botn) b4 = *reinterpret_cast<const float4*>(pc + o.y);
        if (xt)   rtx = pc[o.z];
        if (xb)   rbx = pc[o.w];

        float v = t4.x * wt4.x + t4.y * wt4.y + t4.z * wt4.z + t4.w * wt4.w
                + b4.x * wb4.x + b4.y * wb4.y + b4.z * wb4.z + b4.w * wb4.w
                + rtx * wx.x + rbx * wx.y;
        ob[(size_t)c * NBIN] = fmaxf(v, 0.0f);
    }
}

extern "C" void kernel_launch(void* const* d_in, const int* in_sizes, int n_in,
                              void* d_out, int out_size) {
    const float* x     = (const float*)d_in[0];   // (2,256,256,256) f32
    const float* boxes = (const float*)d_in[1];   // (2,512,5) f32
    float* out = (float*)d_out;                   // (1024,256,7,7) f32
    (void)in_sizes; (void)n_in; (void)out_size;

    rroi_pool_kernel<<<NUM_B * NUM_N * 2, 256>>>(x, boxes, out);
}